// round 1
// baseline (speedup 1.0000x reference)
#include <cuda_runtime.h>
#include <math.h>

#define NBATCH 256
#define CCH    256
#define VDIM   25
#define TDIM   20
#define C4DIM  64
#define ODIM   256
#define EPSV   1e-5f

// Scratch (no cudaMalloc allowed)
__device__ float g_pooled[NBATCH * CCH * TDIM];   // (N, C, T)
__device__ float g_l     [NBATCH * CCH * TDIM];   // (N, C, T) sigmoid gate
__device__ float g_kern  [NBATCH * CCH * 3];      // (N, C, K) softmax kernel

// ---------- packed f32x2 helpers (FFMA2 on sm_103a) ----------
__device__ __forceinline__ void ffma2(unsigned long long &d,
                                      unsigned long long a,
                                      unsigned long long b) {
    asm("fma.rn.f32x2 %0, %1, %2, %0;" : "+l"(d) : "l"(a), "l"(b));
}
__device__ __forceinline__ unsigned long long dup2(float w) {
    unsigned long long r;
    asm("mov.b64 %0, {%1, %1};" : "=l"(r) : "f"(w));
    return r;
}
__device__ __forceinline__ void unpack2(unsigned long long v, float &lo, float &hi) {
    asm("mov.b64 {%0, %1}, %2;" : "=f"(lo), "=f"(hi) : "l"(v));
}

// ============================================================
// K1: pooled[n,c,t] = mean_v x[n,c,v,t]
// 1 warp per (n,c) row; coalesced 2000B row load into smem, reduce.
// ============================================================
__global__ void __launch_bounds__(256) k_pool(const float* __restrict__ x) {
    __shared__ float sx[8][VDIM * TDIM];   // 16 KB
    const int w    = threadIdx.x >> 5;
    const int lane = threadIdx.x & 31;
    const long row = (long)blockIdx.x * 8 + w;
    const float* src = x + row * (VDIM * TDIM);
    for (int i = lane; i < VDIM * TDIM; i += 32) sx[w][i] = src[i];
    __syncwarp();
    if (lane < TDIM) {
        float s = 0.f;
        #pragma unroll
        for (int v = 0; v < VDIM; v++) s += sx[w][v * TDIM + lane];
        g_pooled[row * TDIM + lane] = s * (1.f / VDIM);
    }
}

// ============================================================
// K2: G branch (kern) + L branch (l), one block per n.
// ============================================================
__global__ void __launch_bounds__(256) k_branches(
    const float* __restrict__ Wg1, const float* __restrict__ Wg2,
    const float* __restrict__ Wl1, const float* __restrict__ Wl2,
    const float* __restrict__ bng, const float* __restrict__ bnl)
{
    __shared__ float p_s[CCH][TDIM + 2];   // zero-padded pooled, 22.5 KB
    __shared__ float l1_s[C4DIM][TDIM];    // 5 KB
    __shared__ float wg1_s[40 * 20];
    __shared__ float wg2_s[3 * 40];
    __shared__ float Ag[40], Bg[40];

    const int n   = blockIdx.x;
    const int tid = threadIdx.x;

    // loads
    {
        const float* pp = g_pooled + ((long)n * CCH + tid) * TDIM;
        p_s[tid][0] = 0.f;
        p_s[tid][TDIM + 1] = 0.f;
        #pragma unroll
        for (int t = 0; t < TDIM; t++) p_s[tid][1 + t] = pp[t];
    }
    for (int i = tid; i < 800; i += 256) wg1_s[i] = Wg1[i];
    if (tid < 120) wg2_s[tid] = Wg2[tid];
    if (tid < 40) {
        float g = bng[tid], b = bng[40 + tid], m = bng[80 + tid], v = bng[120 + tid];
        float a = g * rsqrtf(v + EPSV);
        Ag[tid] = a;
        Bg[tid] = b - m * a;
    }
    __syncthreads();

    // ---- G branch: thread = channel c ----
    {
        const int c = tid;
        float h[40];
        #pragma unroll
        for (int i = 0; i < 40; i++) {
            float s = 0.f;
            #pragma unroll
            for (int t = 0; t < TDIM; t++)
                s = fmaf(wg1_s[i * TDIM + t], p_s[c][1 + t], s);
            h[i] = fmaxf(fmaf(Ag[i], s, Bg[i]), 0.f);
        }
        float z0 = 0.f, z1 = 0.f, z2 = 0.f;
        #pragma unroll
        for (int i = 0; i < 40; i++) {
            z0 = fmaf(wg2_s[i],      h[i], z0);
            z1 = fmaf(wg2_s[40 + i], h[i], z1);
            z2 = fmaf(wg2_s[80 + i], h[i], z2);
        }
        float mx = fmaxf(z0, fmaxf(z1, z2));
        float e0 = expf(z0 - mx), e1 = expf(z1 - mx), e2 = expf(z2 - mx);
        float inv = 1.f / (e0 + e1 + e2);
        long kb = ((long)n * CCH + c) * 3;
        g_kern[kb + 0] = e0 * inv;
        g_kern[kb + 1] = e1 * inv;
        g_kern[kb + 2] = e2 * inv;
    }

    // ---- L branch stage 1: l1[j,t] = relu(bn(conv1d(pooled))) ----
    {
        const int j  = tid >> 2;       // 0..63
        const int tq = tid & 3;        // 5 t's each
        float acc[5] = {0.f, 0.f, 0.f, 0.f, 0.f};
        const float* wl = Wl1 + (long)j * CCH * 3;
        for (int c = 0; c < CCH; c++) {
            float w0 = wl[c * 3], w1 = wl[c * 3 + 1], w2 = wl[c * 3 + 2];
            #pragma unroll
            for (int u = 0; u < 5; u++) {
                int t = tq * 5 + u;            // output t: uses pooled[t-1..t+1] = p_s[t..t+2]
                acc[u] = fmaf(w0, p_s[c][t],     acc[u]);
                acc[u] = fmaf(w1, p_s[c][t + 1], acc[u]);
                acc[u] = fmaf(w2, p_s[c][t + 2], acc[u]);
            }
        }
        float g = bnl[j], b = bnl[64 + j], m = bnl[128 + j], v = bnl[192 + j];
        float a  = g * rsqrtf(v + EPSV);
        float bb = b - m * a;
        #pragma unroll
        for (int u = 0; u < 5; u++)
            l1_s[j][tq * 5 + u] = fmaxf(fmaf(a, acc[u], bb), 0.f);
    }
    __syncthreads();

    // ---- L branch stage 2: l[c,t] = sigmoid(Wl2 @ l1) ----
    {
        const int c = tid;
        float acc[TDIM];
        #pragma unroll
        for (int t = 0; t < TDIM; t++) acc[t] = 0.f;
        const float* w = Wl2 + c * C4DIM;
        for (int j = 0; j < C4DIM; j++) {
            float wv = w[j];
            #pragma unroll
            for (int t = 0; t < TDIM; t++)
                acc[t] = fmaf(wv, l1_s[j][t], acc[t]);
        }
        float* lo = g_l + ((long)n * CCH + c) * TDIM;
        #pragma unroll
        for (int t = 0; t < TDIM; t++)
            lo[t] = 1.f / (1.f + expf(-acc[t]));
    }
}

// ============================================================
// K3: fused dynamic depthwise conv + bn1+relu + 1x1 conv + bn2+relu
// block = (v-slab of NV, n). Phase 1: thread=c builds mid tile in smem.
// Phase 2: thread=o, 256-deep dot via broadcast LDS + FFMA2.
// ============================================================
template <int NV>
__global__ void __launch_bounds__(256) k_main(
    const float* __restrict__ x, const float* __restrict__ Wc2,
    const float* __restrict__ bn1p, const float* __restrict__ bn2p,
    float* __restrict__ out)
{
    constexpr int NP = NV * TDIM;                    // positions per block
    __shared__ __align__(16) float mid_s[CCH][NP];   // 40 KB (NV=2)

    const int n  = blockIdx.y;
    const int v0 = (NV == 2) ? blockIdx.x * 2 : (VDIM - 1);

    // ---------- Phase 1: mid ----------
    {
        const int c   = threadIdx.x;
        const long ncb = (long)n * CCH + c;
        float g = bn1p[c], be = bn1p[CCH + c], mu = bn1p[2 * CCH + c], va = bn1p[3 * CCH + c];
        float a1 = g * rsqrtf(va + EPSV);
        float b1 = be - mu * a1;
        float k0 = g_kern[ncb * 3 + 0];
        float k1 = g_kern[ncb * 3 + 1];
        float k2 = g_kern[ncb * 3 + 2];

        float lr[TDIM];
        const float4* lp = (const float4*)(g_l + ncb * TDIM);
        #pragma unroll
        for (int q = 0; q < TDIM / 4; q++) {
            float4 t4 = lp[q];
            lr[4 * q + 0] = t4.x; lr[4 * q + 1] = t4.y;
            lr[4 * q + 2] = t4.z; lr[4 * q + 3] = t4.w;
        }

        #pragma unroll
        for (int vi = 0; vi < NV; vi++) {
            const int v = v0 + vi;
            const float4* xp = (const float4*)(x + (ncb * VDIM + v) * TDIM);
            float s[TDIM + 2];
            s[0] = 0.f; s[TDIM + 1] = 0.f;     // zero padding of (x + l)
            #pragma unroll
            for (int q = 0; q < TDIM / 4; q++) {
                float4 t4 = xp[q];
                s[4 * q + 1] = t4.x + lr[4 * q + 0];
                s[4 * q + 2] = t4.y + lr[4 * q + 1];
                s[4 * q + 3] = t4.z + lr[4 * q + 2];
                s[4 * q + 4] = t4.w + lr[4 * q + 3];
            }
            #pragma unroll
            for (int t = 0; t < TDIM; t++) {
                float m = k0 * s[t] + k1 * s[t + 1] + k2 * s[t + 2];
                mid_s[threadIdx.x][vi * TDIM + t] = fmaxf(fmaf(a1, m, b1), 0.f);
            }
        }
    }
    __syncthreads();

    // ---------- Phase 2: 1x1 conv (FFMA2, broadcast smem reads) ----------
    {
        const int o = threadIdx.x;
        float g = bn2p[o], be = bn2p[ODIM + o], mu = bn2p[2 * ODIM + o], va = bn2p[3 * ODIM + o];
        float a2 = g * rsqrtf(va + EPSV);
        float b2 = be - mu * a2;

        unsigned long long acc[NP / 2];
        #pragma unroll
        for (int i = 0; i < NP / 2; i++) acc[i] = 0ull;

        const float4* wp = (const float4*)(Wc2 + o * CCH);
        #pragma unroll 2
        for (int cq = 0; cq < CCH / 4; cq++) {
            float4 w4 = __ldg(&wp[cq]);
            #pragma unroll
            for (int j = 0; j < 4; j++) {
                float wj = (j == 0) ? w4.x : (j == 1) ? w4.y : (j == 2) ? w4.z : w4.w;
                unsigned long long w2 = dup2(wj);
                const ulonglong2* mrow = (const ulonglong2*)(&mid_s[cq * 4 + j][0]);
                #pragma unroll
                for (int p = 0; p < NP / 4; p++) {
                    ulonglong2 m2 = mrow[p];          // LDS.128 broadcast: 4 floats
                    ffma2(acc[2 * p + 0], w2, m2.x);
                    ffma2(acc[2 * p + 1], w2, m2.y);
                }
            }
        }

        #pragma unroll
        for (int p = 0; p < NP / 2; p++) {
            float lo, hi;
            unpack2(acc[p], lo, hi);
            float r0 = fmaxf(fmaf(a2, lo, b2), 0.f);
            float r1 = fmaxf(fmaf(a2, hi, b2), 0.f);
            int pos = 2 * p;
            int vi  = pos / TDIM;
            int t   = pos % TDIM;
            float2* op = (float2*)(out + (((long)n * ODIM + o) * VDIM + (v0 + vi)) * TDIM + t);
            *op = make_float2(r0, r1);
        }
    }
}

// ============================================================
extern "C" void kernel_launch(void* const* d_in, const int* in_sizes, int n_in,
                              void* d_out, int out_size) {
    const float* x    = (const float*)d_in[0];
    const float* Wg1  = (const float*)d_in[1];
    const float* Wg2  = (const float*)d_in[2];
    const float* Wl1  = (const float*)d_in[3];
    const float* Wl2  = (const float*)d_in[4];
    const float* Wc2  = (const float*)d_in[5];
    const float* bng  = (const float*)d_in[6];
    const float* bnl  = (const float*)d_in[7];
    const float* bn1p = (const float*)d_in[8];
    const float* bn2p = (const float*)d_in[9];
    float* out = (float*)d_out;

    k_pool<<<NBATCH * CCH / 8, 256>>>(x);
    k_branches<<<NBATCH, 256>>>(Wg1, Wg2, Wl1, Wl2, bng, bnl);
    k_main<2><<<dim3(12, NBATCH), 256>>>(x, Wc2, bn1p, bn2p, out);   // v = 0..23
    k_main<1><<<dim3(1,  NBATCH), 256>>>(x, Wc2, bn1p, bn2p, out);   // v = 24
}